// round 4
// baseline (speedup 1.0000x reference)
#include <cuda_runtime.h>
#include <math.h>

#define N_NODES 100000
#define PAD     128      // max in-degree slots per node (Poisson(32): P(>=128) ~ e-85)
#define F_IN    512
#define DIM     32
#define NCLS    40

// ---------------- scratch (static device memory; no allocations) ----------------
__device__ int   g_is64;                            // 1 if edge_index is int64
__device__ int   g_deg[N_NODES];
__device__ int   g_cur[N_NODES];
__device__ float g_dinv[N_NODES];
__device__ int   g_bucket[(size_t)N_NODES * PAD];   // 51.2 MB
__device__ float g_xws[(size_t)N_NODES * DIM];      // dinv * (x @ W1)
__device__ float g_hs [(size_t)N_NODES * DIM];      // dinv * relu(agg1 + b1)
__device__ float g_z  [(size_t)N_NODES * DIM];      // agg2 (pre-W2)

// ---------------- edge dtype detection ----------------
// If data is int64 (values < 2^31), every odd 32-bit word is 0.
// If data is int32 (random node ids), odd words are random: P(all 32 zero) ~ 1e-160.
__global__ void k_detect(const int* __restrict__ ei32) {
    if (threadIdx.x == 0 && blockIdx.x == 0) {
        int nz = 0;
#pragma unroll
        for (int i = 0; i < 32; i++) nz |= ei32[2 * i + 1];
        g_is64 = (nz == 0) ? 1 : 0;
    }
}

// ---------------- setup kernels ----------------
__global__ void k_init() {
    int i = blockIdx.x * blockDim.x + threadIdx.x;
    if (i < N_NODES) { g_deg[i] = 1; g_cur[i] = 0; }   // deg starts at 1 (self loop)
}

__device__ __forceinline__ int load_edge(const void* ei, size_t idx, int is64) {
    if (is64) return (int)((const long long*)ei)[idx];
    return ((const int*)ei)[idx];
}

__global__ void k_deg(const void* __restrict__ ei, int E) {
    int t = blockIdx.x * blockDim.x + threadIdx.x;
    if (t < E) {
        int dst = load_edge(ei, (size_t)E + t, g_is64);
        if ((unsigned)dst < N_NODES) atomicAdd(&g_deg[dst], 1);
    }
}

__global__ void k_dinv() {
    int i = blockIdx.x * blockDim.x + threadIdx.x;
    if (i < N_NODES) g_dinv[i] = rsqrtf((float)g_deg[i]);
}

__global__ void k_scatter(const void* __restrict__ ei, int E) {
    int t = blockIdx.x * blockDim.x + threadIdx.x;
    if (t < E) {
        int is64 = g_is64;
        int src = load_edge(ei, (size_t)t, is64);
        int dst = load_edge(ei, (size_t)E + t, is64);
        if ((unsigned)dst < N_NODES && (unsigned)src < N_NODES) {
            int p = atomicAdd(&g_cur[dst], 1);
            if (p < PAD) g_bucket[(size_t)dst * PAD + p] = src;
        }
    }
}

// ---------------- GEMM1: xws = dinv * (x @ W1) ----------------
// warp per 8 rows; lane = output column. W1 column cached in regs per 16-k chunk.
__global__ void k_gemm1(const float* __restrict__ x, const float* __restrict__ W1) {
    int warp = (blockIdx.x * blockDim.x + threadIdx.x) >> 5;
    int lane = threadIdx.x & 31;
    int row0 = warp * 8;
    if (row0 >= N_NODES) return;   // N_NODES % 8 == 0: no partial warps

    float acc[8];
#pragma unroll
    for (int r = 0; r < 8; r++) acc[r] = 0.f;

    for (int kc = 0; kc < F_IN; kc += 16) {
        float w[16];
#pragma unroll
        for (int i = 0; i < 16; i++) w[i] = __ldg(&W1[(kc + i) * DIM + lane]);
#pragma unroll
        for (int r = 0; r < 8; r++) {
            const float4* xp = (const float4*)(x + (size_t)(row0 + r) * F_IN + kc);
            float4 a = xp[0], b = xp[1], c = xp[2], d = xp[3];
            float s = a.x * w[0];
            s = fmaf(a.y, w[1], s);  s = fmaf(a.z, w[2], s);  s = fmaf(a.w, w[3], s);
            s = fmaf(b.x, w[4], s);  s = fmaf(b.y, w[5], s);  s = fmaf(b.z, w[6], s);  s = fmaf(b.w, w[7], s);
            s = fmaf(c.x, w[8], s);  s = fmaf(c.y, w[9], s);  s = fmaf(c.z, w[10], s); s = fmaf(c.w, w[11], s);
            s = fmaf(d.x, w[12], s); s = fmaf(d.y, w[13], s); s = fmaf(d.z, w[14], s); s = fmaf(d.w, w[15], s);
            acc[r] += s;
        }
    }
#pragma unroll
    for (int r = 0; r < 8; r++) {
        int row = row0 + r;
        g_xws[(size_t)row * DIM + lane] = g_dinv[row] * acc[r];
    }
}

// ---------------- aggregation ------------------------------------------------
// out[i] = f( dinv[i]*(in[i] + sum_{src in bucket[i]} in[src]) )
// LAYER=1: in=g_xws, out=g_hs, h=relu(di*s + b1[lane]), store di*h.
// LAYER=2: in=g_hs,  out=g_z,  store di*s.
// Buffers resolved INSIDE device code (never pass __device__ symbols from host).
template <int LAYER>
__global__ void k_agg(const float* __restrict__ bias) {
    const float* __restrict__ in  = (LAYER == 1) ? g_xws : g_hs;
    float* __restrict__       out = (LAYER == 1) ? g_hs  : g_z;

    int node = (blockIdx.x * blockDim.x + threadIdx.x) >> 5;
    int lane = threadIdx.x & 31;
    if (node >= N_NODES) return;

    float di = g_dinv[node];
    float s  = in[(size_t)node * DIM + lane];   // self term (dinv[src] folded into `in`)
    int cnt  = g_deg[node] - 1;
    if (cnt > PAD) cnt = PAD;
    const int* bkt = g_bucket + (size_t)node * PAD;

    int e = 0;
    int cnt8 = cnt & ~7;
    for (; e < cnt8; e += 8) {
        int4 ia = *(const int4*)(bkt + e);
        int4 ib = *(const int4*)(bkt + e + 4);
        float v0 = in[(size_t)ia.x * DIM + lane];
        float v1 = in[(size_t)ia.y * DIM + lane];
        float v2 = in[(size_t)ia.z * DIM + lane];
        float v3 = in[(size_t)ia.w * DIM + lane];
        float v4 = in[(size_t)ib.x * DIM + lane];
        float v5 = in[(size_t)ib.y * DIM + lane];
        float v6 = in[(size_t)ib.z * DIM + lane];
        float v7 = in[(size_t)ib.w * DIM + lane];
        s += ((v0 + v1) + (v2 + v3)) + ((v4 + v5) + (v6 + v7));
    }
    for (; e < cnt; e++) {
        s += in[(size_t)bkt[e] * DIM + lane];
    }

    if (LAYER == 1) {
        float h = fmaxf(fmaf(di, s, bias[lane]), 0.f);
        out[(size_t)node * DIM + lane] = di * h;
    } else {
        out[(size_t)node * DIM + lane] = di * s;
    }
}

// ---------------- GEMM2 (32x40) + log_softmax, warp per node ----------------
__global__ void k_out(const float* __restrict__ W2, const float* __restrict__ b2,
                      float* __restrict__ out) {
    __shared__ float W2s[DIM * NCLS];
    __shared__ float b2s[NCLS];
    int t = threadIdx.x;
    for (int i = t; i < DIM * NCLS; i += blockDim.x) W2s[i] = W2[i];
    if (t < NCLS) b2s[t] = b2[t];
    __syncthreads();

    int node = (blockIdx.x * blockDim.x + t) >> 5;
    if (node >= N_NODES) return;
    int lane = t & 31;

    float zv = g_z[(size_t)node * DIM + lane];
    int k2 = (lane < NCLS - 32) ? (lane + 32) : lane;   // valid smem index for all lanes
    float a1 = 0.f, a2 = 0.f;
#pragma unroll
    for (int c = 0; c < DIM; c++) {
        float zc = __shfl_sync(0xffffffffu, zv, c);
        a1 = fmaf(zc, W2s[c * NCLS + lane], a1);
        a2 = fmaf(zc, W2s[c * NCLS + k2],   a2);
    }
    float l1 = a1 + b2s[lane];
    float l2 = a2 + b2s[k2];
    bool has2 = (lane < NCLS - 32);

    float m = has2 ? fmaxf(l1, l2) : l1;
#pragma unroll
    for (int o = 16; o > 0; o >>= 1) m = fmaxf(m, __shfl_xor_sync(0xffffffffu, m, o));

    float esum = __expf(l1 - m) + (has2 ? __expf(l2 - m) : 0.f);
#pragma unroll
    for (int o = 16; o > 0; o >>= 1) esum += __shfl_xor_sync(0xffffffffu, esum, o);

    float ls = m + __logf(esum);
    out[(size_t)node * NCLS + lane] = l1 - ls;
    if (has2) out[(size_t)node * NCLS + 32 + lane] = l2 - ls;
}

// ---------------- launch ----------------
extern "C" void kernel_launch(void* const* d_in, const int* in_sizes, int n_in,
                              void* d_out, int out_size) {
    const float* x  = (const float*)d_in[0];
    const void*  ei = d_in[1];
    const float* W1 = (const float*)d_in[2];
    const float* b1 = (const float*)d_in[3];
    const float* W2 = (const float*)d_in[4];
    const float* b2 = (const float*)d_in[5];
    float*       out = (float*)d_out;

    int E = in_sizes[1] / 2;

    int nb_n = (N_NODES + 255) / 256;
    int nb_e = (E + 255) / 256;

    k_detect<<<1, 32>>>((const int*)ei);
    k_init<<<nb_n, 256>>>();
    k_deg<<<nb_e, 256>>>(ei, E);
    k_dinv<<<nb_n, 256>>>();
    k_scatter<<<nb_e, 256>>>(ei, E);

    // 12500 warps of 8 rows each = 100000 rows; 8 warps/block
    k_gemm1<<<(12500 + 7) / 8, 256>>>(x, W1);

    // 8 nodes (warps) per block -> 12500 blocks covers exactly 100000 nodes
    k_agg<1><<<12500, 256>>>(b1);
    k_agg<2><<<12500, 256>>>(b1);

    k_out<<<12500, 256>>>(W2, b2, out);
}

// round 6
// speedup vs baseline: 1.2338x; 1.2338x over previous
#include <cuda_runtime.h>
#include <math.h>

#define N_NODES 100000
#define PAD     128      // max in-degree slots per node (Poisson(32): P(>=128) ~ e-85)
#define F_IN    512
#define DIM     32
#define NCLS    40

typedef unsigned long long u64;

// packed f32x2 helpers (sm_100+)
#define FMA_F32X2(d, a, b, c) \
    asm("fma.rn.f32x2 %0, %1, %2, %3;" : "=l"(d) : "l"(a), "l"(b), "l"(c))
#define ADD_F32X2(d, a, b) \
    asm("add.rn.f32x2 %0, %1, %2;" : "=l"(d) : "l"(a), "l"(b))

__device__ __forceinline__ u64 pack_f32x2(float lo, float hi) {
    u64 r;
    asm("mov.b64 %0, {%1, %2};" : "=l"(r) : "r"(__float_as_uint(lo)), "r"(__float_as_uint(hi)));
    return r;
}
__device__ __forceinline__ void unpack_f32x2(u64 v, float& lo, float& hi) {
    unsigned int l, h;
    asm("mov.b64 {%0, %1}, %2;" : "=r"(l), "=r"(h) : "l"(v));
    lo = __uint_as_float(l); hi = __uint_as_float(h);
}

// ---------------- scratch (static device memory; no allocations) ----------------
__device__ int   g_is64;                            // 1 if edge_index is int64
__device__ int   g_cur[N_NODES];                    // in-degree (excl. self loop)
__device__ float g_dinv[N_NODES];
__device__ int   g_bucket[(size_t)N_NODES * PAD];   // 51.2 MB
__device__ float g_xws[(size_t)N_NODES * DIM];      // dinv * (x @ W1)
__device__ float g_hs [(size_t)N_NODES * DIM];      // dinv * relu(agg1 + b1)
__device__ float g_z  [(size_t)N_NODES * DIM];      // agg2 (pre-W2)

// ---------------- edge dtype detection ----------------
// int64 values < 2^31 -> every odd 32-bit word is 0; int32 random ids -> not.
__global__ void k_detect(const int* __restrict__ ei32) {
    if (threadIdx.x == 0 && blockIdx.x == 0) {
        int nz = 0;
#pragma unroll
        for (int i = 0; i < 32; i++) nz |= ei32[2 * i + 1];
        g_is64 = (nz == 0) ? 1 : 0;
    }
}

__global__ void k_init() {
    int i = blockIdx.x * blockDim.x + threadIdx.x;
    if (i < N_NODES) g_cur[i] = 0;
}

__device__ __forceinline__ int load_edge(const void* ei, size_t idx, int is64) {
    if (is64) return (int)((const long long*)ei)[idx];
    return ((const int*)ei)[idx];
}

// single edge pass: count + scatter
__global__ void k_scatter(const void* __restrict__ ei, int E) {
    int t = blockIdx.x * blockDim.x + threadIdx.x;
    if (t < E) {
        int is64 = g_is64;
        int src = load_edge(ei, (size_t)t, is64);
        int dst = load_edge(ei, (size_t)E + t, is64);
        if ((unsigned)dst < N_NODES && (unsigned)src < N_NODES) {
            int p = atomicAdd(&g_cur[dst], 1);
            if (p < PAD) g_bucket[(size_t)dst * PAD + p] = src;
        }
    }
}

__global__ void k_dinv() {
    int i = blockIdx.x * blockDim.x + threadIdx.x;
    if (i < N_NODES) g_dinv[i] = rsqrtf((float)(g_cur[i] + 1));   // +1 self loop
}

// ---------------- GEMM1: xws = dinv * (x @ W1), FFMA2 packed along k --------
// warp per 8 rows; lane = output column. LDG.128 of x reinterprets directly as
// two f32x2 operands; w pairs packed once per 8-k chunk (shared by all 8 rows).
__global__ void k_gemm1(const float* __restrict__ x, const float* __restrict__ W1) {
    int warp = (blockIdx.x * blockDim.x + threadIdx.x) >> 5;
    int lane = threadIdx.x & 31;
    int row0 = warp * 8;
    if (row0 >= N_NODES) return;   // N_NODES % 8 == 0

    u64 acc[8];
#pragma unroll
    for (int r = 0; r < 8; r++) acc[r] = 0ull;   // {0.f, 0.f}

    for (int kc = 0; kc < F_IN; kc += 8) {
        float w0 = __ldg(&W1[(kc + 0) * DIM + lane]);
        float w1 = __ldg(&W1[(kc + 1) * DIM + lane]);
        float w2 = __ldg(&W1[(kc + 2) * DIM + lane]);
        float w3 = __ldg(&W1[(kc + 3) * DIM + lane]);
        float w4 = __ldg(&W1[(kc + 4) * DIM + lane]);
        float w5 = __ldg(&W1[(kc + 5) * DIM + lane]);
        float w6 = __ldg(&W1[(kc + 6) * DIM + lane]);
        float w7 = __ldg(&W1[(kc + 7) * DIM + lane]);
        u64 wp0 = pack_f32x2(w0, w1);
        u64 wp1 = pack_f32x2(w2, w3);
        u64 wp2 = pack_f32x2(w4, w5);
        u64 wp3 = pack_f32x2(w6, w7);
#pragma unroll
        for (int r = 0; r < 8; r++) {
            const ulonglong2* xp = (const ulonglong2*)(x + (size_t)(row0 + r) * F_IN + kc);
            ulonglong2 p0 = xp[0];   // k..k+3 as two f32x2
            ulonglong2 p1 = xp[1];   // k+4..k+7
            FMA_F32X2(acc[r], p0.x, wp0, acc[r]);
            FMA_F32X2(acc[r], p0.y, wp1, acc[r]);
            FMA_F32X2(acc[r], p1.x, wp2, acc[r]);
            FMA_F32X2(acc[r], p1.y, wp3, acc[r]);
        }
    }
#pragma unroll
    for (int r = 0; r < 8; r++) {
        int row = row0 + r;
        float lo, hi;
        unpack_f32x2(acc[r], lo, hi);
        g_xws[(size_t)row * DIM + lane] = g_dinv[row] * (lo + hi);
    }
}

// ---------------- aggregation ------------------------------------------------
// half-warp per node, lane = feature PAIR (float2). One LDG.64 instruction
// gathers for 2 edges (one per half-warp); f32x2 add halves the FADD count.
// LAYER=1: in=g_xws, out=g_hs, h=relu(di*s + b1), store di*h.
// LAYER=2: in=g_hs,  out=g_z,  store di*s.
template <int LAYER>
__global__ void k_agg(const float* __restrict__ bias) {
    const float* __restrict__ in  = (LAYER == 1) ? g_xws : g_hs;
    float* __restrict__       out = (LAYER == 1) ? g_hs  : g_z;
    const u64* __restrict__   in2 = (const u64*)in;

    int gw   = (blockIdx.x * blockDim.x + threadIdx.x) >> 5;   // warp id < 50000
    int lane = threadIdx.x & 31;
    int h    = lane >> 4;           // half id: 0 or 1
    int hl   = lane & 15;           // lane within half = feature pair
    int node = gw * 2 + h;
    if (node >= N_NODES) return;

    float di = g_dinv[node];
    u64 s = in2[(size_t)node * 16 + hl];   // self term
    int cnt = g_cur[node];
    if (cnt > PAD) cnt = PAD;
    const int* bkt = g_bucket + (size_t)node * PAD;

    // warp-uniform trip count (max over the two halves)
    int cntmax = max(cnt, __shfl_xor_sync(0xffffffffu, cnt, 16));

    for (int e = 0; e < cntmax; e += 4) {
#pragma unroll
        for (int i = 0; i < 4; i++) {
            if (e + i < cnt) {
                int src = bkt[e + i];                       // broadcast within half
                u64 v = in2[(size_t)src * 16 + hl];         // LDG.64, coalesced per half
                ADD_F32X2(s, s, v);
            }
        }
    }

    float lo, hi;
    unpack_f32x2(s, lo, hi);
    float* op = out + (size_t)node * DIM + hl * 2;
    if (LAYER == 1) {
        float2 bp = ((const float2*)bias)[hl];
        float h0 = fmaxf(fmaf(di, lo, bp.x), 0.f);
        float h1 = fmaxf(fmaf(di, hi, bp.y), 0.f);
        op[0] = di * h0;
        op[1] = di * h1;
    } else {
        op[0] = di * lo;
        op[1] = di * hi;
    }
}

// ---------------- GEMM2 (32x40) + log_softmax, warp per node ----------------
__global__ void k_out(const float* __restrict__ W2, const float* __restrict__ b2,
                      float* __restrict__ out) {
    __shared__ float W2s[DIM * NCLS];
    __shared__ float b2s[NCLS];
    int t = threadIdx.x;
    for (int i = t; i < DIM * NCLS; i += blockDim.x) W2s[i] = W2[i];
    if (t < NCLS) b2s[t] = b2[t];
    __syncthreads();

    int node = (blockIdx.x * blockDim.x + t) >> 5;
    if (node >= N_NODES) return;
    int lane = t & 31;

    float zv = g_z[(size_t)node * DIM + lane];
    int k2 = (lane < NCLS - 32) ? (lane + 32) : lane;   // valid smem index for all lanes
    float a1 = 0.f, a2 = 0.f;
#pragma unroll
    for (int c = 0; c < DIM; c++) {
        float zc = __shfl_sync(0xffffffffu, zv, c);
        a1 = fmaf(zc, W2s[c * NCLS + lane], a1);
        a2 = fmaf(zc, W2s[c * NCLS + k2],   a2);
    }
    float l1 = a1 + b2s[lane];
    float l2 = a2 + b2s[k2];
    bool has2 = (lane < NCLS - 32);

    float m = has2 ? fmaxf(l1, l2) : l1;
#pragma unroll
    for (int o = 16; o > 0; o >>= 1) m = fmaxf(m, __shfl_xor_sync(0xffffffffu, m, o));

    float esum = __expf(l1 - m) + (has2 ? __expf(l2 - m) : 0.f);
#pragma unroll
    for (int o = 16; o > 0; o >>= 1) esum += __shfl_xor_sync(0xffffffffu, esum, o);

    float ls = m + __logf(esum);
    out[(size_t)node * NCLS + lane] = l1 - ls;
    if (has2) out[(size_t)node * NCLS + 32 + lane] = l2 - ls;
}

// ---------------- launch ----------------
extern "C" void kernel_launch(void* const* d_in, const int* in_sizes, int n_in,
                              void* d_out, int out_size) {
    const float* x  = (const float*)d_in[0];
    const void*  ei = d_in[1];
    const float* W1 = (const float*)d_in[2];
    const float* b1 = (const float*)d_in[3];
    const float* W2 = (const float*)d_in[4];
    const float* b2 = (const float*)d_in[5];
    float*       out = (float*)d_out;

    int E = in_sizes[1] / 2;

    int nb_n = (N_NODES + 255) / 256;
    int nb_e = (E + 255) / 256;

    k_detect<<<1, 32>>>((const int*)ei);
    k_init<<<nb_n, 256>>>();
    k_scatter<<<nb_e, 256>>>(ei, E);
    k_dinv<<<nb_n, 256>>>();

    // 12500 warps of 8 rows each = 100000 rows; 8 warps/block
    k_gemm1<<<(12500 + 7) / 8, 256>>>(x, W1);

    // half-warp per node: 50000 warps, 8 warps/block -> 6250 blocks
    k_agg<1><<<6250, 256>>>(b1);
    k_agg<2><<<6250, 256>>>(b1);

    k_out<<<12500, 256>>>(W2, b2, out);
}

// round 8
// speedup vs baseline: 1.7614x; 1.4277x over previous
#include <cuda_runtime.h>
#include <math.h>

#define N_NODES 100000
#define PAD     128
#define F_IN    512
#define DIM     32
#define NCLS    40
#define TM      128     // gemm1 rows per block
#define KT      64      // gemm1 k-tile

typedef unsigned long long u64;

#define FMA_F32X2(d, a, b, c) \
    asm("fma.rn.f32x2 %0, %1, %2, %3;" : "=l"(d) : "l"(a), "l"(b), "l"(c))
#define ADD_F32X2(d, a, b) \
    asm("add.rn.f32x2 %0, %1, %2;" : "=l"(d) : "l"(a), "l"(b))

__device__ __forceinline__ void unpack_f32x2(u64 v, float& lo, float& hi) {
    unsigned int l, h;
    asm("mov.b64 {%0, %1}, %2;" : "=r"(l), "=r"(h) : "l"(v));
    lo = __uint_as_float(l); hi = __uint_as_float(h);
}

// ---------------- scratch ----------------
__device__ int   g_is64;
__device__ int   g_cur[N_NODES];                    // in-degree (excl. self loop)
__device__ float g_dinv[N_NODES];
__device__ int   g_bucket[(size_t)N_NODES * PAD];
__device__ float g_xws[(size_t)N_NODES * DIM];
__device__ float g_hs [(size_t)N_NODES * DIM];
__device__ float g_z  [(size_t)N_NODES * DIM];

// ---------------- edge dtype detection ----------------
__global__ void k_detect(const int* __restrict__ ei32) {
    if (threadIdx.x == 0 && blockIdx.x == 0) {
        int nz = 0;
#pragma unroll
        for (int i = 0; i < 32; i++) nz |= ei32[2 * i + 1];
        g_is64 = (nz == 0) ? 1 : 0;
    }
}

__global__ void k_init() {
    int i = blockIdx.x * blockDim.x + threadIdx.x;
    if (i < N_NODES) g_cur[i] = 0;
}

// 2 edges per thread, vectorized loads. counts + scatters in one pass.
__global__ void k_scatter(const void* __restrict__ ei, int E) {
    int t = blockIdx.x * blockDim.x + threadIdx.x;
    int e0 = t * 2;
    if (e0 >= E) return;
    int is64 = g_is64;
    int s0, s1, d0, d1;
    bool two = (e0 + 1 < E);
    if (is64) {
        const longlong2* p = (const longlong2*)ei;
        longlong2 sv = p[t];                       // src[e0], src[e0+1]
        longlong2 dv = p[(E >> 1) + t];            // E even (3.2M); dst stream
        s0 = (int)sv.x; s1 = (int)sv.y;
        d0 = (int)dv.x; d1 = (int)dv.y;
    } else {
        const int2* p = (const int2*)ei;
        int2 sv = p[t];
        int2 dv = p[(E >> 1) + t];
        s0 = sv.x; s1 = sv.y;
        d0 = dv.x; d1 = dv.y;
    }
    if ((unsigned)d0 < N_NODES && (unsigned)s0 < N_NODES) {
        int p0 = atomicAdd(&g_cur[d0], 1);
        if (p0 < PAD) g_bucket[(size_t)d0 * PAD + p0] = s0;
    }
    if (two && (unsigned)d1 < N_NODES && (unsigned)s1 < N_NODES) {
        int p1 = atomicAdd(&g_cur[d1], 1);
        if (p1 < PAD) g_bucket[(size_t)d1 * PAD + p1] = s1;
    }
}

__global__ void k_dinv() {
    int i = blockIdx.x * blockDim.x + threadIdx.x;
    if (i < N_NODES) g_dinv[i] = rsqrtf((float)(g_cur[i] + 1));
}

// ---------------- GEMM1: xws = dinv * (x @ W1), smem-tiled -------------------
// block: 128 rows x 32 cols, k-tile 64. 256 threads, each an 8x2 register tile.
// W tile transposed to [col][k] (padded stride 66) so k-pairs are contiguous
// for f32x2 operands.
__global__ __launch_bounds__(256) void k_gemm1(const float* __restrict__ x,
                                               const float* __restrict__ W1) {
    __shared__ float xs[TM][KT];          // 32 KB
    __shared__ float wt[DIM][KT + 2];     // 8.25 KB, padded stride 66
    int t = threadIdx.x;
    int row0 = blockIdx.x * TM;

    int rt = t >> 4;          // 0..15
    int ct = t & 15;          // 0..15
    int r0 = rt * 8;          // tile-local first row
    int c0 = ct * 2;

    u64 acc[8][2];
#pragma unroll
    for (int i = 0; i < 8; i++) { acc[i][0] = 0ull; acc[i][1] = 0ull; }

    for (int kc = 0; kc < F_IN; kc += KT) {
        __syncthreads();
        // load x tile: 128x64 floats = 2048 float4, 8 per thread, coalesced
#pragma unroll
        for (int i = 0; i < 8; i++) {
            int lin = t + i * 256;        // float4 slot
            int row = lin >> 4;           // 0..127
            int f4  = lin & 15;           // 0..15
            int grow = row0 + row;
            float4 v = make_float4(0.f, 0.f, 0.f, 0.f);
            if (grow < N_NODES)
                v = *(const float4*)&x[(size_t)grow * F_IN + kc + f4 * 4];
            *(float4*)&xs[row][f4 * 4] = v;
        }
        // load + transpose W tile: 64x32 floats, 8 per thread
#pragma unroll
        for (int i = 0; i < 8; i++) {
            int lin = t + i * 256;        // 0..2047
            int k   = lin >> 5;           // 0..63
            int col = lin & 31;
            wt[col][k] = W1[(size_t)(kc + k) * DIM + col];
        }
        __syncthreads();

#pragma unroll 4
        for (int kp = 0; kp < KT / 2; kp++) {
            u64 wv0 = *(const u64*)&wt[c0][kp * 2];
            u64 wv1 = *(const u64*)&wt[c0 + 1][kp * 2];
#pragma unroll
            for (int i = 0; i < 8; i++) {
                u64 xv = *(const u64*)&xs[r0 + i][kp * 2];
                FMA_F32X2(acc[i][0], xv, wv0, acc[i][0]);
                FMA_F32X2(acc[i][1], xv, wv1, acc[i][1]);
            }
        }
    }

#pragma unroll
    for (int i = 0; i < 8; i++) {
        int row = row0 + r0 + i;
        if (row < N_NODES) {
            float di = g_dinv[row];
            float l0, h0, l1, h1;
            unpack_f32x2(acc[i][0], l0, h0);
            unpack_f32x2(acc[i][1], l1, h1);
            float2 o = make_float2(di * (l0 + h0), di * (l1 + h1));
            *(float2*)&g_xws[(size_t)row * DIM + c0] = o;
        }
    }
}

// ---------------- aggregation (half-warp per node, f32x2 lanes) --------------
template <int LAYER>
__global__ void k_agg(const float* __restrict__ bias) {
    const float* __restrict__ in  = (LAYER == 1) ? g_xws : g_hs;
    float* __restrict__       out = (LAYER == 1) ? g_hs  : g_z;
    const u64* __restrict__   in2 = (const u64*)in;

    int gw   = (blockIdx.x * blockDim.x + threadIdx.x) >> 5;
    int lane = threadIdx.x & 31;
    int h    = lane >> 4;
    int hl   = lane & 15;
    int node = gw * 2 + h;
    if (node >= N_NODES) return;

    float di = g_dinv[node];
    u64 s = in2[(size_t)node * 16 + hl];
    int cnt = g_cur[node];
    if (cnt > PAD) cnt = PAD;
    const int* bkt = g_bucket + (size_t)node * PAD;

    int cntmax = max(cnt, __shfl_xor_sync(0xffffffffu, cnt, 16));

    for (int e = 0; e < cntmax; e += 4) {
#pragma unroll
        for (int i = 0; i < 4; i++) {
            if (e + i < cnt) {
                int src = bkt[e + i];
                u64 v = in2[(size_t)src * 16 + hl];
                ADD_F32X2(s, s, v);
            }
        }
    }

    float lo, hi;
    unpack_f32x2(s, lo, hi);
    float* op = out + (size_t)node * DIM + hl * 2;
    if (LAYER == 1) {
        float2 bp = ((const float2*)bias)[hl];
        float h0 = fmaxf(fmaf(di, lo, bp.x), 0.f);
        float h1 = fmaxf(fmaf(di, hi, bp.y), 0.f);
        op[0] = di * h0;
        op[1] = di * h1;
    } else {
        op[0] = di * lo;
        op[1] = di * hi;
    }
}

// ---------------- GEMM2 (32x40) + log_softmax, warp per node ----------------
__global__ void k_out(const float* __restrict__ W2, const float* __restrict__ b2,
                      float* __restrict__ out) {
    __shared__ float W2s[DIM * NCLS];
    __shared__ float b2s[NCLS];
    int t = threadIdx.x;
    for (int i = t; i < DIM * NCLS; i += blockDim.x) W2s[i] = W2[i];
    if (t < NCLS) b2s[t] = b2[t];
    __syncthreads();

    int node = (blockIdx.x * blockDim.x + t) >> 5;
    if (node >= N_NODES) return;
    int lane = t & 31;

    float zv = g_z[(size_t)node * DIM + lane];
    int k2 = (lane < NCLS - 32) ? (lane + 32) : lane;
    float a1 = 0.f, a2 = 0.f;
#pragma unroll
    for (int c = 0; c < DIM; c++) {
        float zc = __shfl_sync(0xffffffffu, zv, c);
        a1 = fmaf(zc, W2s[c * NCLS + lane], a1);
        a2 = fmaf(zc, W2s[c * NCLS + k2],   a2);
    }
    float l1 = a1 + b2s[lane];
    float l2 = a2 + b2s[k2];
    bool has2 = (lane < NCLS - 32);

    float m = has2 ? fmaxf(l1, l2) : l1;
#pragma unroll
    for (int o = 16; o > 0; o >>= 1) m = fmaxf(m, __shfl_xor_sync(0xffffffffu, m, o));

    float esum = __expf(l1 - m) + (has2 ? __expf(l2 - m) : 0.f);
#pragma unroll
    for (int o = 16; o > 0; o >>= 1) esum += __shfl_xor_sync(0xffffffffu, esum, o);

    float ls = m + __logf(esum);
    out[(size_t)node * NCLS + lane] = l1 - ls;
    if (has2) out[(size_t)node * NCLS + 32 + lane] = l2 - ls;
}

// ---------------- launch ----------------
extern "C" void kernel_launch(void* const* d_in, const int* in_sizes, int n_in,
                              void* d_out, int out_size) {
    const float* x  = (const float*)d_in[0];
    const void*  ei = d_in[1];
    const float* W1 = (const float*)d_in[2];
    const float* b1 = (const float*)d_in[3];
    const float* W2 = (const float*)d_in[4];
    const float* b2 = (const float*)d_in[5];
    float*       out = (float*)d_out;

    int E = in_sizes[1] / 2;

    int nb_n = (N_NODES + 255) / 256;
    int nb_e2 = ((E + 1) / 2 + 255) / 256;   // 2 edges per thread

    k_detect<<<1, 32>>>((const int*)ei);
    k_init<<<nb_n, 256>>>();
    k_scatter<<<nb_e2, 256>>>(ei, E);
    k_dinv<<<nb_n, 256>>>();

    k_gemm1<<<(N_NODES + TM - 1) / TM, 256>>>(x, W1);

    k_agg<1><<<6250, 256>>>(b1);
    k_agg<2><<<6250, 256>>>(b1);

    k_out<<<12500, 256>>>(W2, b2, out);
}